// round 2
// baseline (speedup 1.0000x reference)
#include <cuda_runtime.h>
#include <math.h>

#define BB 128
#define SS 512
#define DD 768
#define PP 60
#define LL 5
#define KK 5
#define D4 (DD/4)            // 192
#define SEQ_OUT (KK*LL + SS) // 537
#define NCHUNK 8
#define CHUNK_S (SS/NCHUNK)  // 64

#define MAP_SCALE 0.1f
#define MAX_NORM (1.0f - 4e-3f)

// Output layout (float32, concatenated in reference return order)
#define OFF_PE  0LL
#define N_PE    ((long long)BB*SEQ_OUT*DD)           // 52,801,536
#define OFF_RS  (N_PE)                               // 52,801,536
#define OFF_IDX (OFF_RS + 1)                         // 52,801,537
#define OFF_SIM (OFF_IDX + (long long)BB*KK)         // 52,802,177
#define OFF_SK  (OFF_SIM + (long long)BB*PP)         // 52,809,857

// Scratch (device globals -> no allocation)
__device__ float g_xpart[BB*NCHUNK*DD];
__device__ float g_qball[BB*DD];
__device__ float g_keyball[PP*DD];
__device__ float g_x2[BB];
__device__ float g_y2[PP];
__device__ float g_persum[BB];
__device__ int   g_idx[BB*KK];

// ---------------------------------------------------------------------------
// Kernel 1: copy x_embed into prompted_embedding slot + per-chunk partial sums
// grid (NCHUNK, BB), 192 threads (one float4 column per thread)
// ---------------------------------------------------------------------------
__global__ void k1_copy_partial(const float4* __restrict__ xe, float4* __restrict__ out) {
    int chunk = blockIdx.x, b = blockIdx.y, t = threadIdx.x;
    const float4* src = xe + ((size_t)b * SS + (size_t)chunk * CHUNK_S) * D4 + t;
    float4* dst = out + ((size_t)b * SEQ_OUT + KK*LL + (size_t)chunk * CHUNK_S) * D4 + t;
    float4 acc = make_float4(0.f, 0.f, 0.f, 0.f);
#pragma unroll 4
    for (int s = 0; s < CHUNK_S; s++) {
        float4 v = src[(size_t)s * D4];
        acc.x += v.x; acc.y += v.y; acc.z += v.z; acc.w += v.w;
        dst[(size_t)s * D4] = v;
    }
    ((float4*)g_xpart)[(b * NCHUNK + chunk) * D4 + t] = acc;
}

// ---------------------------------------------------------------------------
// Block reduction helper (192 threads = 6 warps)
// ---------------------------------------------------------------------------
__device__ __forceinline__ float block_reduce_192(float v) {
    __shared__ float sh[6];
    __shared__ float total;
    int lane = threadIdx.x & 31, wid = threadIdx.x >> 5;
#pragma unroll
    for (int o = 16; o > 0; o >>= 1) v += __shfl_down_sync(0xffffffffu, v, o);
    if (lane == 0) sh[wid] = v;
    __syncthreads();
    if (threadIdx.x == 0) {
        float s = 0.f;
#pragma unroll
        for (int i = 0; i < 6; i++) s += sh[i];
        total = s;
    }
    __syncthreads();
    return total;
}

// ---------------------------------------------------------------------------
// Kernel 2: map_to_ball for x_mean (blocks 0..127) and prompt_key (128..187)
// 192 threads, float4 per thread
// ---------------------------------------------------------------------------
__global__ void k2_ball(const float4* __restrict__ pkey) {
    int id = blockIdx.x, t = threadIdx.x;
    float4 v;
    if (id < BB) {
        const float4* pp = (const float4*)g_xpart;
        float sx = 0.f, sy = 0.f, sz = 0.f, sw = 0.f;
#pragma unroll
        for (int c = 0; c < NCHUNK; c++) {
            float4 a = pp[(id*NCHUNK + c) * D4 + t];
            sx += a.x; sy += a.y; sz += a.z; sw += a.w;
        }
        const float inv_s = 1.0f / (float)SS;
        v = make_float4(sx * inv_s, sy * inv_s, sz * inv_s, sw * inv_s);
    } else {
        v = pkey[(id - BB) * D4 + t];
    }
    float ssl = v.x*v.x + v.y*v.y + v.z*v.z + v.w*v.w;
    float ss = block_reduce_192(ssl);
    // _l2_normalize: x * rsqrt(max(ss, 1e-12))
    float inv = rsqrtf(fmaxf(ss, 1e-12f));
    // u = l2norm(x) * MAP_SCALE ;  n = sqrt(max(sum u^2, 1e-15))
    float n = sqrtf(fmaxf(ss * inv * inv * (MAP_SCALE*MAP_SCALE), 1e-15f));
    float th = tanhf(n);
    float scale = th / n;                        // expmap0 coefficient on u
    float factor = (th > MAX_NORM) ? (MAX_NORM / th) : 1.0f;  // proju0
    float coeff = inv * MAP_SCALE * scale * factor;
    float nf = th * factor;                      // final norm
    float4 q = make_float4(v.x*coeff, v.y*coeff, v.z*coeff, v.w*coeff);
    if (id < BB) {
        ((float4*)g_qball)[id * D4 + t] = q;
        if (t == 0) g_x2[id] = nf * nf;
    } else {
        ((float4*)g_keyball)[(id - BB) * D4 + t] = q;
        if (t == 0) g_y2[id - BB] = nf * nf;
    }
}

// ---------------------------------------------------------------------------
// Kernel 3: distances, similarity, top-K, idx, per-batch selected-dist sum
// one block per batch, 256 threads (8 warps, warp-per-key)
// ---------------------------------------------------------------------------
__global__ void k3_dist_topk(float* __restrict__ out) {
    int b = blockIdx.x;
    __shared__ float qsh[DD];
    __shared__ float dsh[PP];
    for (int i = threadIdx.x; i < DD; i += 256) qsh[i] = g_qball[b * DD + i];
    __syncthreads();
    int warp = threadIdx.x >> 5, lane = threadIdx.x & 31;
    float x2 = g_x2[b];
    for (int p = warp; p < PP; p += 8) {
        float sum = 0.f;
        for (int j = lane; j < DD; j += 32) sum += qsh[j] * g_keyball[p * DD + j];
#pragma unroll
        for (int o = 16; o > 0; o >>= 1) sum += __shfl_down_sync(0xffffffffu, sum, o);
        if (lane == 0) {
            float y2 = g_y2[p];
            float xy = sum;
            // d = mobius_add(-x, y): only scalar invariants needed
            float A   = 1.f - 2.f*xy + y2;
            float Bc  = 1.f - x2;
            float den = fmaxf(1.f - 2.f*xy + x2*y2, 1e-15f);
            float n2  = (A*A*x2 - 2.f*A*Bc*xy + Bc*Bc*y2) / (den*den);
            float n   = sqrtf(fmaxf(n2, 1e-15f));
            n = fminf(n, 1.f - 1e-7f);
            float dist = 2.f * atanhf(n);
            dsh[p] = dist;
            out[OFF_SIM + (long long)b * PP + p] = -dist;
        }
    }
    __syncthreads();
    if (threadIdx.x == 0) {
        int sel[KK];
        bool used[PP];
        for (int p = 0; p < PP; p++) used[p] = false;
        float sum = 0.f;
        for (int k = 0; k < KK; k++) {
            float best = 1e30f; int bi = 0;
            for (int p = 0; p < PP; p++)
                if (!used[p] && dsh[p] < best) { best = dsh[p]; bi = p; }
            used[bi] = true; sel[k] = bi; sum += best;
        }
        // sort ascending
        for (int i = 0; i < KK; i++)
            for (int j = i + 1; j < KK; j++)
                if (sel[j] < sel[i]) { int tmp = sel[i]; sel[i] = sel[j]; sel[j] = tmp; }
        for (int k = 0; k < KK; k++) {
            g_idx[b * KK + k] = sel[k];
            out[OFF_IDX + (long long)b * KK + k] = (float)sel[k];
        }
        g_persum[b] = sum;
    }
}

// ---------------------------------------------------------------------------
// Kernel 4: gather prompt[idx] into prompted_embedding + selected_key
// grid (KK, BB), 192 threads
// ---------------------------------------------------------------------------
__global__ void k4_gather(const float4* __restrict__ prompt, float* __restrict__ out) {
    int k = blockIdx.x, b = blockIdx.y, t = threadIdx.x;
    int j = g_idx[b * KK + k];
    const float4* src = prompt + (size_t)j * LL * D4;
    float4* dst = (float4*)out + ((size_t)b * SEQ_OUT + (size_t)k * LL) * D4;
#pragma unroll
    for (int l = 0; l < LL; l++) dst[(size_t)l * D4 + t] = src[(size_t)l * D4 + t];
    // selected_key region has odd base offset -> scalar stores
    const float* kb = g_keyball + (size_t)j * DD;
    float* sk = out + OFF_SK + ((size_t)b * KK + k) * DD;
    for (int i = t; i < DD; i += 192) sk[i] = kb[i];
}

// ---------------------------------------------------------------------------
// Kernel 5: reduce_sim = sum(persum)/B   (1 block, 128 threads)
// ---------------------------------------------------------------------------
__global__ void k5_reduce_sim(float* __restrict__ out) {
    __shared__ float sh[4];
    float v = g_persum[threadIdx.x];
    int lane = threadIdx.x & 31, wid = threadIdx.x >> 5;
#pragma unroll
    for (int o = 16; o > 0; o >>= 1) v += __shfl_down_sync(0xffffffffu, v, o);
    if (lane == 0) sh[wid] = v;
    __syncthreads();
    if (threadIdx.x == 0) {
        float s = sh[0] + sh[1] + sh[2] + sh[3];
        out[OFF_RS] = s * (1.0f / (float)BB);
    }
}

extern "C" void kernel_launch(void* const* d_in, const int* in_sizes, int n_in,
                              void* d_out, int out_size) {
    // Identify inputs by element count (defensive against ordering surprises)
    const float* x_embed = nullptr;    // 128*512*768 = 50,331,648
    const float* prompt = nullptr;     // 60*5*768   = 230,400
    const float* prompt_key = nullptr; // 60*768     = 46,080
    for (int i = 0; i < n_in; i++) {
        if (in_sizes[i] == BB*SS*DD)        x_embed    = (const float*)d_in[i];
        else if (in_sizes[i] == PP*LL*DD)   prompt     = (const float*)d_in[i];
        else if (in_sizes[i] == PP*DD)      prompt_key = (const float*)d_in[i];
    }
    float* out = (float*)d_out;

    dim3 g1(NCHUNK, BB);
    k1_copy_partial<<<g1, D4>>>((const float4*)x_embed, (float4*)out);
    k2_ball<<<BB + PP, D4>>>((const float4*)prompt_key);
    k3_dist_topk<<<BB, 256>>>(out);
    dim3 g4(KK, BB);
    k4_gather<<<g4, D4>>>((const float4*)prompt, out);
    k5_reduce_sim<<<1, BB>>>(out);
}

// round 3
// speedup vs baseline: 1.0662x; 1.0662x over previous
#include <cuda_runtime.h>
#include <math.h>

#define BB 128
#define SS 512
#define DD 768
#define PP 60
#define LL 5
#define KK 5
#define D4 (DD/4)            // 192
#define SEQ_OUT (KK*LL + SS) // 537
#define NCHUNK 16
#define CHUNK_S (SS/NCHUNK)  // 32

#define MAP_SCALE 0.1f
#define MAX_NORM (1.0f - 4e-3f)

// Output layout (float32, concatenated in reference return order)
#define N_PE    ((long long)BB*SEQ_OUT*DD)           // 52,801,536
#define OFF_RS  (N_PE)
#define OFF_IDX (OFF_RS + 1)
#define OFF_SIM (OFF_IDX + (long long)BB*KK)
#define OFF_SK  (OFF_SIM + (long long)BB*PP)

// Scratch (device globals -> no allocation)
__device__ float g_xpart[BB*NCHUNK*DD];
__device__ float g_keyball[PP*DD];
__device__ float g_persum[BB];
__device__ int   g_idx[BB*KK];

// ---------------------------------------------------------------------------
// Kernel 1: copy x_embed into prompted_embedding slot + per-chunk partial sums
// grid (NCHUNK, BB), 192 threads (one float4 column per thread)
// ---------------------------------------------------------------------------
__global__ void k1_copy_partial(const float4* __restrict__ xe, float4* __restrict__ out) {
    int chunk = blockIdx.x, b = blockIdx.y, t = threadIdx.x;
    const float4* src = xe + ((size_t)b * SS + (size_t)chunk * CHUNK_S) * D4 + t;
    float4* dst = out + ((size_t)b * SEQ_OUT + KK*LL + (size_t)chunk * CHUNK_S) * D4 + t;
    float4 acc = make_float4(0.f, 0.f, 0.f, 0.f);
#pragma unroll 8
    for (int s = 0; s < CHUNK_S; s++) {
        float4 v = src[(size_t)s * D4];
        acc.x += v.x; acc.y += v.y; acc.z += v.z; acc.w += v.w;
        dst[(size_t)s * D4] = v;
    }
    ((float4*)g_xpart)[(b * NCHUNK + chunk) * D4 + t] = acc;
}

// ---------------------------------------------------------------------------
// Kernel 2: fused map-to-ball + distances + similarity + top-K per batch.
// one block per batch, 256 threads (8 warps, warp-per-key).
// Block 0 additionally materializes g_keyball for the gather kernel.
// ---------------------------------------------------------------------------
__global__ void k2_dist_topk(const float* __restrict__ pkey, float* __restrict__ out) {
    int b = blockIdx.x;
    int tid = threadIdx.x, lane = tid & 31, warp = tid >> 5;
    __shared__ float qsh[DD];
    __shared__ float dsh[PP];
    __shared__ float redsh[8];
    __shared__ float x2sh;

    // ---- q = map_to_ball(mean(x_embed[b])) ----
    float m[3];
    float local = 0.f;
#pragma unroll
    for (int r = 0; r < 3; r++) {
        int d = tid + r * 256;
        float s = 0.f;
#pragma unroll
        for (int c = 0; c < NCHUNK; c++) s += g_xpart[(b * NCHUNK + c) * DD + d];
        s *= (1.0f / (float)SS);
        m[r] = s;
        local += s * s;
    }
#pragma unroll
    for (int o = 16; o > 0; o >>= 1) local += __shfl_xor_sync(0xffffffffu, local, o);
    if (lane == 0) redsh[warp] = local;
    __syncthreads();
    if (tid == 0) {
        float ssq = 0.f;
#pragma unroll
        for (int i = 0; i < 8; i++) ssq += redsh[i];
        float inv = rsqrtf(fmaxf(ssq, 1e-12f));
        float n = sqrtf(fmaxf(ssq * inv * inv * (MAP_SCALE*MAP_SCALE), 1e-15f));
        float th = tanhf(n);
        float factor = (th > MAX_NORM) ? (MAX_NORM / th) : 1.0f;
        float nf = th * factor;
        x2sh = nf * nf;
        redsh[0] = inv * MAP_SCALE * (th / n) * factor;   // coeff for q
    }
    __syncthreads();
    float coeffq = redsh[0];
#pragma unroll
    for (int r = 0; r < 3; r++) qsh[tid + r * 256] = m[r] * coeffq;
    __syncthreads();
    float x2 = x2sh;

    // ---- per-key: map-to-ball scalars + dot with q (warp per key) ----
    for (int p = warp; p < PP; p += 8) {
        const float* kr = pkey + (size_t)p * DD;
        float ssq = 0.f, dot = 0.f;
        for (int j = lane; j < DD; j += 32) {
            float kv = kr[j];
            ssq += kv * kv;
            dot += kv * qsh[j];
        }
#pragma unroll
        for (int o = 16; o > 0; o >>= 1) {
            ssq += __shfl_xor_sync(0xffffffffu, ssq, o);
            dot += __shfl_xor_sync(0xffffffffu, dot, o);
        }
        float inv = rsqrtf(fmaxf(ssq, 1e-12f));
        float n = sqrtf(fmaxf(ssq * inv * inv * (MAP_SCALE*MAP_SCALE), 1e-15f));
        float th = tanhf(n);
        float factor = (th > MAX_NORM) ? (MAX_NORM / th) : 1.0f;
        float coeffk = inv * MAP_SCALE * (th / n) * factor;
        float nf = th * factor;
        float y2 = nf * nf;
        if (b == 0) {  // materialize key_ball once for the gather kernel
            for (int j = lane; j < DD; j += 32) g_keyball[p * DD + j] = kr[j] * coeffk;
        }
        if (lane == 0) {
            float xy = dot * coeffk;   // dot(q_ball, key_ball)
            float A   = 1.f - 2.f*xy + y2;
            float Bc  = 1.f - x2;
            float den = fmaxf(1.f - 2.f*xy + x2*y2, 1e-15f);
            float n2  = (A*A*x2 - 2.f*A*Bc*xy + Bc*Bc*y2) / (den*den);
            float nn  = sqrtf(fmaxf(n2, 1e-15f));
            nn = fminf(nn, 1.f - 1e-7f);
            float dist = 2.f * atanhf(nn);
            dsh[p] = dist;
            out[OFF_SIM + (long long)b * PP + p] = -dist;
        }
    }
    __syncthreads();

    // ---- top-K (smallest dist), sort idx, per-batch sum ----
    if (tid == 0) {
        int sel[KK];
        bool used[PP];
        for (int p = 0; p < PP; p++) used[p] = false;
        float sum = 0.f;
        for (int k = 0; k < KK; k++) {
            float best = 1e30f; int bi = 0;
            for (int p = 0; p < PP; p++)
                if (!used[p] && dsh[p] < best) { best = dsh[p]; bi = p; }
            used[bi] = true; sel[k] = bi; sum += best;
        }
        for (int i = 0; i < KK; i++)
            for (int j = i + 1; j < KK; j++)
                if (sel[j] < sel[i]) { int tmp = sel[i]; sel[i] = sel[j]; sel[j] = tmp; }
        for (int k = 0; k < KK; k++) {
            g_idx[b * KK + k] = sel[k];
            out[OFF_IDX + (long long)b * KK + k] = (float)sel[k];
        }
        g_persum[b] = sum;
    }
}

// ---------------------------------------------------------------------------
// Kernel 3: gather prompt[idx] + selected_key + reduce_sim.
// grid (KK*LL + KK = 30, BB), 192 threads; one output row per block.
// ---------------------------------------------------------------------------
__global__ void k3_gather(const float4* __restrict__ prompt, float* __restrict__ out) {
    int r = blockIdx.x, b = blockIdx.y, t = threadIdx.x;
    if (r < KK*LL) {
        int k = r / LL, l = r % LL;
        int j = g_idx[b * KK + k];
        float4 v = prompt[((size_t)j * LL + l) * D4 + t];
        ((float4*)out)[((size_t)b * SEQ_OUT + r) * D4 + t] = v;
    } else {
        int k = r - KK*LL;
        int j = g_idx[b * KK + k];
        const float* kb = g_keyball + (size_t)j * DD;
        float* sk = out + OFF_SK + ((size_t)b * KK + k) * DD;
#pragma unroll
        for (int i = t; i < DD; i += 192) sk[i] = kb[i];
    }
    if (r == 0 && b == 0 && t == 0) {
        float s = 0.f;
#pragma unroll 8
        for (int i = 0; i < BB; i++) s += g_persum[i];
        out[OFF_RS] = s * (1.0f / (float)BB);
    }
}

extern "C" void kernel_launch(void* const* d_in, const int* in_sizes, int n_in,
                              void* d_out, int out_size) {
    const float* x_embed = nullptr;    // 128*512*768
    const float* prompt = nullptr;     // 60*5*768
    const float* prompt_key = nullptr; // 60*768
    for (int i = 0; i < n_in; i++) {
        if (in_sizes[i] == BB*SS*DD)        x_embed    = (const float*)d_in[i];
        else if (in_sizes[i] == PP*LL*DD)   prompt     = (const float*)d_in[i];
        else if (in_sizes[i] == PP*DD)      prompt_key = (const float*)d_in[i];
    }
    float* out = (float*)d_out;

    dim3 g1(NCHUNK, BB);
    k1_copy_partial<<<g1, D4>>>((const float4*)x_embed, (float4*)out);
    k2_dist_topk<<<BB, 256>>>(prompt_key, out);
    dim3 g3(KK*LL + KK, BB);
    k3_gather<<<g3, D4>>>((const float4*)prompt, out);
}